// round 5
// baseline (speedup 1.0000x reference)
#include <cuda_runtime.h>
#include <cstdint>
#include <cstddef>

#define N_ATOMS 10000
#define N_PAIRS 250000
#define NP 128
#define NO 128

#define PXNEW_OFF ((size_t)0)
#define IX_OFF    ((size_t)N_ATOMS * 3 * NP)
#define DOT_OFF   (IX_OFF + (size_t)N_PAIRS * 3 * NP)

#define ATOMS_PB 4
#define NBLK (N_ATOMS / ATOMS_PB)
#define CAP 128          // per-atom pair capacity (max seg ~50 expected)

// ---- device scratch (allocation-free; zero-initialized at load) ----
__device__ int g_count[N_ATOMS];     // invariant: zero at entry (k_scan restores)
__device__ int g_offset[N_ATOMS + 1];
__device__ int g_cursor[N_ATOMS];
__device__ int g_pairs[N_PAIRS];

// ---------------------------------------------------------------------------
__global__ void k_hist(const int4* __restrict__ ind2v) {
    int p = blockIdx.x * blockDim.x + threadIdx.x;
    if (p < N_PAIRS / 2) {
        int4 v = ind2v[p];
        atomicAdd(&g_count[v.x], 1);
        atomicAdd(&g_count[v.z], 1);
    }
}

__global__ void k_scan() {
    __shared__ int sb[1024];
    const int CH = 10;
    int t = threadIdx.x;
    int base = t * CH;
    int c[CH];
    int local = 0;
#pragma unroll
    for (int i = 0; i < CH; i++) {
        int idx = base + i;
        c[i] = (idx < N_ATOMS) ? g_count[idx] : 0;
        if (idx < N_ATOMS) g_count[idx] = 0;   // restore zero invariant
        local += c[i];
    }
    sb[t] = local;
    __syncthreads();
    for (int o = 1; o < 1024; o <<= 1) {
        int v = (t >= o) ? sb[t - o] : 0;
        __syncthreads();
        sb[t] += v;
        __syncthreads();
    }
    int run = sb[t] - local;
#pragma unroll
    for (int i = 0; i < CH; i++) {
        int idx = base + i;
        if (idx < N_ATOMS) {
            g_offset[idx] = run;
            g_cursor[idx] = run;
            run += c[i];
        }
    }
    if (t == 1023) g_offset[N_ATOMS] = sb[1023];
}

__global__ void k_scatter(const int4* __restrict__ ind2v) {
    int p = blockIdx.x * blockDim.x + threadIdx.x;
    if (p < N_PAIRS / 2) {
        int4 v = ind2v[p];
        int pos0 = atomicAdd(&g_cursor[v.x], 1);
        int pos1 = atomicAdd(&g_cursor[v.z], 1);
        g_pairs[pos0] = 2 * p;
        g_pairs[pos1] = 2 * p + 1;
    }
}

// ---------------------------------------------------------------------------
// k_main: block = 4 atoms, 512 threads = 16 warps.
// Pair phase: atom al (= t>>7) handled by its own 4-warp group, R3-style:
//   warp y (= (t>>5)&3) strides pairs by 4, lanes own 4 channels (float4).
// GEMM phase: 4 warps, warp g owns cols [32g,32g+32), full p=128, all 12 rows
//   -> w_pp read once per block (64 KB for 4 atoms), scalar loads, no reduction.
__global__ void __launch_bounds__(512, 2)
k_main(const int* __restrict__ ind2,
       const float* __restrict__ px,
       const float* __restrict__ i1,
       const float* __restrict__ diff,
       const float* __restrict__ wpp,
       float* __restrict__ out) {
    __shared__ int   s_pairs[ATOMS_PB][CAP];
    __shared__ int   s_j[ATOMS_PB][CAP];
    __shared__ float s_d[3][ATOMS_PB][CAP];
    __shared__ __align__(16) float s_part[ATOMS_PB][4][3][NP];  // per-y partials
    __shared__ __align__(16) float s_fin[ATOMS_PB][3][NP];      // segment sums

    const int blk = blockIdx.x;
    const int t = threadIdx.x;
    const int l = t & 31;
    const int al = t >> 7;          // local atom 0..3
    const int gt = t & 127;         // thread within atom group
    const int y  = (t >> 5) & 3;    // warp within atom group
    const int q0 = 4 * l;

    const int a    = blk * ATOMS_PB + al;
    const int beg  = g_offset[a];
    const int cnt0 = g_offset[a + 1] - beg;
    const int cnt  = cnt0 < CAP ? cnt0 : CAP;

    // ---- load pair ids (one per thread; cnt <= 128) ----
    if (gt < cnt) s_pairs[al][gt] = g_pairs[beg + gt];
    __syncthreads();

    // ---- O(n^2) rank sort, one element per thread (deterministic order) ----
    int v = 0, r = 0;
    if (gt < cnt) {
        v = s_pairs[al][gt];
        for (int m = 0; m < cnt; m++) r += (s_pairs[al][m] < v);
    }
    __syncthreads();
    if (gt < cnt) s_pairs[al][r] = v;
    __syncthreads();

    // ---- prefetch j and diff (parallel gathers, high MLP) ----
    if (gt < cnt) {
        int pr = s_pairs[al][gt];
        s_j[al][gt]    = __ldg(&ind2[2 * pr + 1]);
        s_d[0][al][gt] = __ldg(&diff[3 * pr + 0]);
        s_d[1][al][gt] = __ldg(&diff[3 * pr + 1]);
        s_d[2][al][gt] = __ldg(&diff[3 * pr + 2]);
    }
    __syncthreads();

    float* out_ix = out + IX_OFF;

    float4 acc0 = make_float4(0.f, 0.f, 0.f, 0.f);
    float4 acc1 = acc0, acc2 = acc0;

    // ---- pair loop (R3 shape): warp y strides by 4, 2x unrolled ----
    int k = y;
    for (; k + 4 < cnt; k += 8) {
        int prA = s_pairs[al][k],     jA = s_j[al][k];
        int prB = s_pairs[al][k + 4], jB = s_j[al][k + 4];
        float dA0 = s_d[0][al][k],     dA1 = s_d[1][al][k],     dA2 = s_d[2][al][k];
        float dB0 = s_d[0][al][k + 4], dB1 = s_d[1][al][k + 4], dB2 = s_d[2][al][k + 4];

        float4 sA = __ldcs((const float4*)(i1 + (size_t)prA * NP + q0));
        float4 sB = __ldcs((const float4*)(i1 + (size_t)prB * NP + q0));
        const float* pjA = px + (size_t)jA * 3 * NP + q0;
        const float* pjB = px + (size_t)jB * 3 * NP + q0;
        float4 a0 = __ldg((const float4*)(pjA));
        float4 a1 = __ldg((const float4*)(pjA + NP));
        float4 a2 = __ldg((const float4*)(pjA + 2 * NP));
        float4 b0 = __ldg((const float4*)(pjB));
        float4 b1 = __ldg((const float4*)(pjB + NP));
        float4 b2 = __ldg((const float4*)(pjB + 2 * NP));

        float4 vA0, vA1, vA2, vB0, vB1, vB2;
        vA0.x = (a0.x + dA0) * sA.x; vA0.y = (a0.y + dA0) * sA.y;
        vA0.z = (a0.z + dA0) * sA.z; vA0.w = (a0.w + dA0) * sA.w;
        vA1.x = (a1.x + dA1) * sA.x; vA1.y = (a1.y + dA1) * sA.y;
        vA1.z = (a1.z + dA1) * sA.z; vA1.w = (a1.w + dA1) * sA.w;
        vA2.x = (a2.x + dA2) * sA.x; vA2.y = (a2.y + dA2) * sA.y;
        vA2.z = (a2.z + dA2) * sA.z; vA2.w = (a2.w + dA2) * sA.w;
        vB0.x = (b0.x + dB0) * sB.x; vB0.y = (b0.y + dB0) * sB.y;
        vB0.z = (b0.z + dB0) * sB.z; vB0.w = (b0.w + dB0) * sB.w;
        vB1.x = (b1.x + dB1) * sB.x; vB1.y = (b1.y + dB1) * sB.y;
        vB1.z = (b1.z + dB1) * sB.z; vB1.w = (b1.w + dB1) * sB.w;
        vB2.x = (b2.x + dB2) * sB.x; vB2.y = (b2.y + dB2) * sB.y;
        vB2.z = (b2.z + dB2) * sB.z; vB2.w = (b2.w + dB2) * sB.w;

        float* opA = out_ix + (size_t)prA * 3 * NP + q0;
        float* opB = out_ix + (size_t)prB * 3 * NP + q0;
        __stcs((float4*)(opA), vA0);
        __stcs((float4*)(opA + NP), vA1);
        __stcs((float4*)(opA + 2 * NP), vA2);
        __stcs((float4*)(opB), vB0);
        __stcs((float4*)(opB + NP), vB1);
        __stcs((float4*)(opB + 2 * NP), vB2);

        acc0.x += vA0.x + vB0.x; acc0.y += vA0.y + vB0.y;
        acc0.z += vA0.z + vB0.z; acc0.w += vA0.w + vB0.w;
        acc1.x += vA1.x + vB1.x; acc1.y += vA1.y + vB1.y;
        acc1.z += vA1.z + vB1.z; acc1.w += vA1.w + vB1.w;
        acc2.x += vA2.x + vB2.x; acc2.y += vA2.y + vB2.y;
        acc2.z += vA2.z + vB2.z; acc2.w += vA2.w + vB2.w;
    }
    for (; k < cnt0; k += 4) {
        int pr, j;
        float d0, d1, d2;
        if (k < CAP) {
            pr = s_pairs[al][k]; j = s_j[al][k];
            d0 = s_d[0][al][k]; d1 = s_d[1][al][k]; d2 = s_d[2][al][k];
        } else {   // overflow fallback (unreachable for this input)
            pr = g_pairs[beg + k]; j = ind2[2 * pr + 1];
            d0 = diff[3 * pr]; d1 = diff[3 * pr + 1]; d2 = diff[3 * pr + 2];
        }
        float4 s = __ldcs((const float4*)(i1 + (size_t)pr * NP + q0));
        const float* pj = px + (size_t)j * 3 * NP + q0;
        float4 p0 = __ldg((const float4*)(pj));
        float4 p1 = __ldg((const float4*)(pj + NP));
        float4 p2 = __ldg((const float4*)(pj + 2 * NP));

        float4 v0, v1, v2;
        v0.x = (p0.x + d0) * s.x; v0.y = (p0.y + d0) * s.y;
        v0.z = (p0.z + d0) * s.z; v0.w = (p0.w + d0) * s.w;
        v1.x = (p1.x + d1) * s.x; v1.y = (p1.y + d1) * s.y;
        v1.z = (p1.z + d1) * s.z; v1.w = (p1.w + d1) * s.w;
        v2.x = (p2.x + d2) * s.x; v2.y = (p2.y + d2) * s.y;
        v2.z = (p2.z + d2) * s.z; v2.w = (p2.w + d2) * s.w;

        float* op = out_ix + (size_t)pr * 3 * NP + q0;
        __stcs((float4*)(op), v0);
        __stcs((float4*)(op + NP), v1);
        __stcs((float4*)(op + 2 * NP), v2);

        acc0.x += v0.x; acc0.y += v0.y; acc0.z += v0.z; acc0.w += v0.w;
        acc1.x += v1.x; acc1.y += v1.y; acc1.z += v1.z; acc1.w += v1.w;
        acc2.x += v2.x; acc2.y += v2.y; acc2.z += v2.z; acc2.w += v2.w;
    }

    *(float4*)&s_part[al][y][0][q0] = acc0;
    *(float4*)&s_part[al][y][1][q0] = acc1;
    *(float4*)&s_part[al][y][2][q0] = acc2;
    __syncthreads();

    // ---- reduce 4 partials -> s_fin (thread (al,gt) owns channel gt) ----
    {
        float f0 = s_part[al][0][0][gt] + s_part[al][1][0][gt]
                 + s_part[al][2][0][gt] + s_part[al][3][0][gt];
        float f1 = s_part[al][0][1][gt] + s_part[al][1][1][gt]
                 + s_part[al][2][1][gt] + s_part[al][3][1][gt];
        float f2 = s_part[al][0][2][gt] + s_part[al][1][2][gt]
                 + s_part[al][2][2][gt] + s_part[al][3][2][gt];
        s_fin[al][0][gt] = f0;
        s_fin[al][1][gt] = f1;
        s_fin[al][2][gt] = f2;
    }
    __syncthreads();

    // ---- GEMM: 4 warps, warp g owns cols [32g, 32g+32), full p, 12 rows ----
    const int gw = t >> 5;
    if (gw < 4) {
        const int q = 32 * gw + l;      // this thread's output column
        float acc[12];
#pragma unroll
        for (int rr = 0; rr < 12; rr++) acc[rr] = 0.f;

#pragma unroll 4
        for (int p = 0; p < NP; p++) {
            float wv = __ldg(&wpp[(size_t)p * NO + q]);
#pragma unroll
            for (int am = 0; am < 4; am++) {
                acc[3 * am + 0] += s_fin[am][0][p] * wv;
                acc[3 * am + 1] += s_fin[am][1][p] * wv;
                acc[3 * am + 2] += s_fin[am][2][p] * wv;
            }
        }

        float* opx = out + PXNEW_OFF;
#pragma unroll
        for (int am = 0; am < 4; am++) {
            float r0 = acc[3 * am + 0];
            float r1 = acc[3 * am + 1];
            float r2 = acc[3 * am + 2];
            size_t row = (size_t)(blk * ATOMS_PB + am) * 3;
            opx[(row + 0) * NP + q] = r0;
            opx[(row + 1) * NP + q] = r1;
            opx[(row + 2) * NP + q] = r2;
            out[DOT_OFF + (size_t)(blk * ATOMS_PB + am) * NO + q] =
                r0 * r0 + r1 * r1 + r2 * r2;
        }
    }
}

// ---------------------------------------------------------------------------
extern "C" void kernel_launch(void* const* d_in, const int* in_sizes, int n_in,
                              void* d_out, int out_size) {
    const int*   ind2 = (const int*)d_in[0];
    const float* px   = (const float*)d_in[1];
    const float* i1   = (const float*)d_in[2];
    const float* diff = (const float*)d_in[3];
    const float* wpp  = (const float*)d_in[4];
    float* out = (float*)d_out;

    k_hist<<<(N_PAIRS / 2 + 255) / 256, 256>>>((const int4*)ind2);
    k_scan<<<1, 1024>>>();
    k_scatter<<<(N_PAIRS / 2 + 255) / 256, 256>>>((const int4*)ind2);
    k_main<<<NBLK, 512>>>(ind2, px, i1, diff, wpp, out);
}

// round 6
// speedup vs baseline: 1.3201x; 1.3201x over previous
#include <cuda_runtime.h>
#include <cstdint>
#include <cstddef>

#define N_ATOMS 10000
#define N_PAIRS 250000
#define NP 128
#define NO 128

#define PXNEW_OFF ((size_t)0)
#define IX_OFF    ((size_t)N_ATOMS * 3 * NP)
#define DOT_OFF   (IX_OFF + (size_t)N_PAIRS * 3 * NP)

#define ATOMS_PB 2
#define NBLK (N_ATOMS / ATOMS_PB)
#define CAP 96           // per-atom smem capacity (max seg ~50 expected)

// ---- device scratch (allocation-free; zero-initialized at load) ----
__device__ int g_count[N_ATOMS];     // invariant: zero at entry (k_scan restores)
__device__ int g_offset[N_ATOMS + 1];
__device__ int g_cursor[N_ATOMS];
__device__ int g_pairs[N_PAIRS];

// ---------------------------------------------------------------------------
__global__ void k_hist(const int2* __restrict__ ind2v) {
    int p = blockIdx.x * blockDim.x + threadIdx.x;
    if (p < N_PAIRS) {
        int2 v = __ldg(&ind2v[p]);
        atomicAdd(&g_count[v.x], 1);
    }
}

__global__ void k_scan() {
    __shared__ int sb[1024];
    const int CH = 10;
    int t = threadIdx.x;
    int base = t * CH;
    int c[CH];
    int local = 0;
#pragma unroll
    for (int i = 0; i < CH; i++) {
        int idx = base + i;
        c[i] = (idx < N_ATOMS) ? g_count[idx] : 0;
        if (idx < N_ATOMS) g_count[idx] = 0;   // restore zero invariant
        local += c[i];
    }
    sb[t] = local;
    __syncthreads();
    for (int o = 1; o < 1024; o <<= 1) {
        int v = (t >= o) ? sb[t - o] : 0;
        __syncthreads();
        sb[t] += v;
        __syncthreads();
    }
    int run = sb[t] - local;
#pragma unroll
    for (int i = 0; i < CH; i++) {
        int idx = base + i;
        if (idx < N_ATOMS) {
            g_offset[idx] = run;
            g_cursor[idx] = run;
            run += c[i];
        }
    }
    if (t == 1023) g_offset[N_ATOMS] = sb[1023];
}

__global__ void k_scatter(const int2* __restrict__ ind2v) {
    int p = blockIdx.x * blockDim.x + threadIdx.x;
    if (p < N_PAIRS) {
        int2 v = __ldg(&ind2v[p]);
        int pos = atomicAdd(&g_cursor[v.x], 1);
        g_pairs[pos] = p;
    }
}

// ---------------------------------------------------------------------------
// k_main: block = 2 atoms processed SEQUENTIALLY by 128 threads (4 warps).
// Pair phase per atom is R3-shaped: warp y strides the atom's pairs by 4.
// GEMM: p-split per warp over 6 rows (both atoms) -> w_pp read once per block.
__global__ void __launch_bounds__(128, 8)
k_main(const int* __restrict__ ind2,
       const float* __restrict__ px,
       const float* __restrict__ i1,
       const float* __restrict__ diff,
       const float* __restrict__ wpp,
       float* __restrict__ out) {
    __shared__ int   s_pairs[ATOMS_PB][CAP];
    __shared__ int   s_j[ATOMS_PB][CAP];
    __shared__ float s_d[3][ATOMS_PB][CAP];
    __shared__ __align__(16) float s_part[4][6][NP];   // partials (also temp buf)
    __shared__ __align__(16) float s_fin[6][NP];       // 2 atoms x 3 rows
    __shared__ int s_begs[3];

    const int blk = blockIdx.x;
    const int t = threadIdx.x;
    const int l = t & 31;
    const int y = t >> 5;
    const int q0 = 4 * l;
    const int a0 = blk * ATOMS_PB;

    if (t < 3) s_begs[t] = g_offset[a0 + t];
    __syncthreads();
    const int beg0 = s_begs[0];
    const int c0 = s_begs[1] - s_begs[0];
    const int c1 = s_begs[2] - s_begs[1];
    const int tot = c0 + c1;

    // ---- load all pair ids into temp (s_part reused as int buffer) ----
    int* lin = (int*)s_part;                 // 3072 ints available
    for (int e = t; e < tot; e += 128) lin[e] = g_pairs[beg0 + e];
    __syncthreads();

    // ---- rank-sort each segment (deterministic order) ----
    for (int e = t; e < tot; e += 128) {
        int al = (e >= c0);
        int sb = al ? c0 : 0;
        int se = al ? tot : c0;
        if (se - sb <= CAP) {
            int v = lin[e];
            int r = 0;
            for (int m = sb; m < se; m++) r += (lin[m] < v);
            s_pairs[al][r] = v;
        }
    }
    __syncthreads();

    // ---- prefetch j and diff (parallel gathers) ----
    for (int e = t; e < tot; e += 128) {
        int al = (e >= c0);
        int k = al ? (e - c0) : e;
        int cc = al ? c1 : c0;
        if (cc <= CAP) {
            int pr = s_pairs[al][k];
            s_j[al][k]    = __ldg(&ind2[2 * pr + 1]);
            s_d[0][al][k] = __ldg(&diff[3 * pr + 0]);
            s_d[1][al][k] = __ldg(&diff[3 * pr + 1]);
            s_d[2][al][k] = __ldg(&diff[3 * pr + 2]);
        }
    }
    __syncthreads();   // also guards lin reuse (s_part staged below)

    float* out_ix = out + IX_OFF;

    // ---- per-atom pair phase (sequential atoms, no cross-atom coupling) ----
#pragma unroll
    for (int al = 0; al < ATOMS_PB; al++) {
        const int beg  = al ? (beg0 + c0) : beg0;
        const int cnt0 = al ? c1 : c0;

        float4 acc0 = make_float4(0.f, 0.f, 0.f, 0.f);
        float4 acc1 = acc0, acc2 = acc0;

        if (cnt0 <= CAP) {
            int k = y;
            for (; k + 4 < cnt0; k += 8) {
                int prA = s_pairs[al][k],     jA = s_j[al][k];
                int prB = s_pairs[al][k + 4], jB = s_j[al][k + 4];
                float dA0 = s_d[0][al][k],     dA1 = s_d[1][al][k],     dA2 = s_d[2][al][k];
                float dB0 = s_d[0][al][k + 4], dB1 = s_d[1][al][k + 4], dB2 = s_d[2][al][k + 4];

                float4 sA = __ldcs((const float4*)(i1 + (size_t)prA * NP + q0));
                float4 sB = __ldcs((const float4*)(i1 + (size_t)prB * NP + q0));
                const float* pjA = px + (size_t)jA * 3 * NP + q0;
                const float* pjB = px + (size_t)jB * 3 * NP + q0;
                float4 a0v = __ldg((const float4*)(pjA));
                float4 a1v = __ldg((const float4*)(pjA + NP));
                float4 a2v = __ldg((const float4*)(pjA + 2 * NP));
                float4 b0v = __ldg((const float4*)(pjB));
                float4 b1v = __ldg((const float4*)(pjB + NP));
                float4 b2v = __ldg((const float4*)(pjB + 2 * NP));

                float4 vA0, vA1, vA2, vB0, vB1, vB2;
                vA0.x = (a0v.x + dA0) * sA.x; vA0.y = (a0v.y + dA0) * sA.y;
                vA0.z = (a0v.z + dA0) * sA.z; vA0.w = (a0v.w + dA0) * sA.w;
                vA1.x = (a1v.x + dA1) * sA.x; vA1.y = (a1v.y + dA1) * sA.y;
                vA1.z = (a1v.z + dA1) * sA.z; vA1.w = (a1v.w + dA1) * sA.w;
                vA2.x = (a2v.x + dA2) * sA.x; vA2.y = (a2v.y + dA2) * sA.y;
                vA2.z = (a2v.z + dA2) * sA.z; vA2.w = (a2v.w + dA2) * sA.w;
                vB0.x = (b0v.x + dB0) * sB.x; vB0.y = (b0v.y + dB0) * sB.y;
                vB0.z = (b0v.z + dB0) * sB.z; vB0.w = (b0v.w + dB0) * sB.w;
                vB1.x = (b1v.x + dB1) * sB.x; vB1.y = (b1v.y + dB1) * sB.y;
                vB1.z = (b1v.z + dB1) * sB.z; vB1.w = (b1v.w + dB1) * sB.w;
                vB2.x = (b2v.x + dB2) * sB.x; vB2.y = (b2v.y + dB2) * sB.y;
                vB2.z = (b2v.z + dB2) * sB.z; vB2.w = (b2v.w + dB2) * sB.w;

                float* opA = out_ix + (size_t)prA * 3 * NP + q0;
                float* opB = out_ix + (size_t)prB * 3 * NP + q0;
                __stcs((float4*)(opA), vA0);
                __stcs((float4*)(opA + NP), vA1);
                __stcs((float4*)(opA + 2 * NP), vA2);
                __stcs((float4*)(opB), vB0);
                __stcs((float4*)(opB + NP), vB1);
                __stcs((float4*)(opB + 2 * NP), vB2);

                acc0.x += vA0.x + vB0.x; acc0.y += vA0.y + vB0.y;
                acc0.z += vA0.z + vB0.z; acc0.w += vA0.w + vB0.w;
                acc1.x += vA1.x + vB1.x; acc1.y += vA1.y + vB1.y;
                acc1.z += vA1.z + vB1.z; acc1.w += vA1.w + vB1.w;
                acc2.x += vA2.x + vB2.x; acc2.y += vA2.y + vB2.y;
                acc2.z += vA2.z + vB2.z; acc2.w += vA2.w + vB2.w;
            }
            for (; k < cnt0; k += 4) {
                int pr = s_pairs[al][k], j = s_j[al][k];
                float d0 = s_d[0][al][k], d1 = s_d[1][al][k], d2 = s_d[2][al][k];
                float4 s = __ldcs((const float4*)(i1 + (size_t)pr * NP + q0));
                const float* pj = px + (size_t)j * 3 * NP + q0;
                float4 p0 = __ldg((const float4*)(pj));
                float4 p1 = __ldg((const float4*)(pj + NP));
                float4 p2 = __ldg((const float4*)(pj + 2 * NP));

                float4 v0, v1, v2;
                v0.x = (p0.x + d0) * s.x; v0.y = (p0.y + d0) * s.y;
                v0.z = (p0.z + d0) * s.z; v0.w = (p0.w + d0) * s.w;
                v1.x = (p1.x + d1) * s.x; v1.y = (p1.y + d1) * s.y;
                v1.z = (p1.z + d1) * s.z; v1.w = (p1.w + d1) * s.w;
                v2.x = (p2.x + d2) * s.x; v2.y = (p2.y + d2) * s.y;
                v2.z = (p2.z + d2) * s.z; v2.w = (p2.w + d2) * s.w;

                float* op = out_ix + (size_t)pr * 3 * NP + q0;
                __stcs((float4*)(op), v0);
                __stcs((float4*)(op + NP), v1);
                __stcs((float4*)(op + 2 * NP), v2);

                acc0.x += v0.x; acc0.y += v0.y; acc0.z += v0.z; acc0.w += v0.w;
                acc1.x += v1.x; acc1.y += v1.y; acc1.z += v1.z; acc1.w += v1.w;
                acc2.x += v2.x; acc2.y += v2.y; acc2.z += v2.z; acc2.w += v2.w;
            }
        } else {
            // oversize segment: entire segment via global path (rare/never)
            for (int k = y; k < cnt0; k += 4) {
                int pr = g_pairs[beg + k];
                int j = __ldg(&ind2[2 * pr + 1]);
                float d0 = __ldg(&diff[3 * pr + 0]);
                float d1 = __ldg(&diff[3 * pr + 1]);
                float d2 = __ldg(&diff[3 * pr + 2]);
                float4 s = __ldcs((const float4*)(i1 + (size_t)pr * NP + q0));
                const float* pj = px + (size_t)j * 3 * NP + q0;
                float4 p0 = __ldg((const float4*)(pj));
                float4 p1 = __ldg((const float4*)(pj + NP));
                float4 p2 = __ldg((const float4*)(pj + 2 * NP));

                float4 v0, v1, v2;
                v0.x = (p0.x + d0) * s.x; v0.y = (p0.y + d0) * s.y;
                v0.z = (p0.z + d0) * s.z; v0.w = (p0.w + d0) * s.w;
                v1.x = (p1.x + d1) * s.x; v1.y = (p1.y + d1) * s.y;
                v1.z = (p1.z + d1) * s.z; v1.w = (p1.w + d1) * s.w;
                v2.x = (p2.x + d2) * s.x; v2.y = (p2.y + d2) * s.y;
                v2.z = (p2.z + d2) * s.z; v2.w = (p2.w + d2) * s.w;

                float* op = out_ix + (size_t)pr * 3 * NP + q0;
                __stcs((float4*)(op), v0);
                __stcs((float4*)(op + NP), v1);
                __stcs((float4*)(op + 2 * NP), v2);

                acc0.x += v0.x; acc0.y += v0.y; acc0.z += v0.z; acc0.w += v0.w;
                acc1.x += v1.x; acc1.y += v1.y; acc1.z += v1.z; acc1.w += v1.w;
                acc2.x += v2.x; acc2.y += v2.y; acc2.z += v2.z; acc2.w += v2.w;
            }
        }

        // stage partials (warp-private slots; no barrier needed between atoms)
        *(float4*)&s_part[y][3 * al + 0][q0] = acc0;
        *(float4*)&s_part[y][3 * al + 1][q0] = acc1;
        *(float4*)&s_part[y][3 * al + 2][q0] = acc2;
    }
    __syncthreads();

    // ---- reduce 4 y-partials -> s_fin (thread t owns channel t) ----
#pragma unroll
    for (int r = 0; r < 6; r++) {
        s_fin[r][t] = s_part[0][r][t] + s_part[1][r][t]
                    + s_part[2][r][t] + s_part[3][r][t];
    }
    __syncthreads();

    // ---- GEMM: warp y owns p-range [32y,32y+32), all 6 rows, float4 cols ----
    float4 g0 = make_float4(0.f, 0.f, 0.f, 0.f);
    float4 g1 = g0, g2 = g0, g3 = g0, g4 = g0, g5 = g0;
    {
        const int pb = 32 * y;
#pragma unroll 4
        for (int pc = pb; pc < pb + 32; pc += 2) {
            float2 f0 = *(const float2*)&s_fin[0][pc];
            float2 f1 = *(const float2*)&s_fin[1][pc];
            float2 f2 = *(const float2*)&s_fin[2][pc];
            float2 f3 = *(const float2*)&s_fin[3][pc];
            float2 f4 = *(const float2*)&s_fin[4][pc];
            float2 f5 = *(const float2*)&s_fin[5][pc];
            float4 w0 = __ldg((const float4*)&wpp[(size_t)pc * NO + q0]);
            float4 w1 = __ldg((const float4*)&wpp[(size_t)(pc + 1) * NO + q0]);

            g0.x += f0.x * w0.x + f0.y * w1.x; g0.y += f0.x * w0.y + f0.y * w1.y;
            g0.z += f0.x * w0.z + f0.y * w1.z; g0.w += f0.x * w0.w + f0.y * w1.w;
            g1.x += f1.x * w0.x + f1.y * w1.x; g1.y += f1.x * w0.y + f1.y * w1.y;
            g1.z += f1.x * w0.z + f1.y * w1.z; g1.w += f1.x * w0.w + f1.y * w1.w;
            g2.x += f2.x * w0.x + f2.y * w1.x; g2.y += f2.x * w0.y + f2.y * w1.y;
            g2.z += f2.x * w0.z + f2.y * w1.z; g2.w += f2.x * w0.w + f2.y * w1.w;
            g3.x += f3.x * w0.x + f3.y * w1.x; g3.y += f3.x * w0.y + f3.y * w1.y;
            g3.z += f3.x * w0.z + f3.y * w1.z; g3.w += f3.x * w0.w + f3.y * w1.w;
            g4.x += f4.x * w0.x + f4.y * w1.x; g4.y += f4.x * w0.y + f4.y * w1.y;
            g4.z += f4.x * w0.z + f4.y * w1.z; g4.w += f4.x * w0.w + f4.y * w1.w;
            g5.x += f5.x * w0.x + f5.y * w1.x; g5.y += f5.x * w0.y + f5.y * w1.y;
            g5.z += f5.x * w0.z + f5.y * w1.z; g5.w += f5.x * w0.w + f5.y * w1.w;
        }
    }
    __syncthreads();   // s_part reuse
    *(float4*)&s_part[y][0][q0] = g0;
    *(float4*)&s_part[y][1][q0] = g1;
    *(float4*)&s_part[y][2][q0] = g2;
    *(float4*)&s_part[y][3][q0] = g3;
    *(float4*)&s_part[y][4][q0] = g4;
    *(float4*)&s_part[y][5][q0] = g5;
    __syncthreads();

    // ---- final reduce over y; write px_new + dotted (thread t = col t) ----
    {
        float v[6];
#pragma unroll
        for (int r = 0; r < 6; r++) {
            v[r] = s_part[0][r][t] + s_part[1][r][t]
                 + s_part[2][r][t] + s_part[3][r][t];
        }
        float* opx = out + PXNEW_OFF + (size_t)a0 * 3 * NP + t;
#pragma unroll
        for (int r = 0; r < 6; r++) opx[(size_t)r * NP] = v[r];
        out[DOT_OFF + (size_t)a0 * NO + t]       = v[0]*v[0] + v[1]*v[1] + v[2]*v[2];
        out[DOT_OFF + (size_t)(a0 + 1) * NO + t] = v[3]*v[3] + v[4]*v[4] + v[5]*v[5];
    }
}

// ---------------------------------------------------------------------------
extern "C" void kernel_launch(void* const* d_in, const int* in_sizes, int n_in,
                              void* d_out, int out_size) {
    const int*   ind2 = (const int*)d_in[0];
    const float* px   = (const float*)d_in[1];
    const float* i1   = (const float*)d_in[2];
    const float* diff = (const float*)d_in[3];
    const float* wpp  = (const float*)d_in[4];
    float* out = (float*)d_out;

    k_hist<<<(N_PAIRS + 255) / 256, 256>>>((const int2*)ind2);
    k_scan<<<1, 1024>>>();
    k_scatter<<<(N_PAIRS + 255) / 256, 256>>>((const int2*)ind2);
    k_main<<<NBLK, 128>>>(ind2, px, i1, diff, wpp, out);
}